// round 2
// baseline (speedup 1.0000x reference)
#include <cuda_runtime.h>

#define NCTA 128
#define NTHR 256
#define TSTEPS 512
#define Bb 64
#define Hh 1024
#define K2H 2048

typedef unsigned long long u64_t;

// Persistent device state (allocation-free scratch). All transposed: [col][row], row=batch.
__device__ float g_sT[9][Hh * Bb];
__device__ float g_hT[Hh * Bb];
__device__ float g_embT[Hh * Bb];
__device__ unsigned g_count = 0;   // monotonic across barriers AND graph replays
__device__ unsigned g_gen = 0;

// DAG metadata: node i uses Ws[i], input states[pred[i]], output states[i+1].
__device__ const int d_pred[8] = {0, 1, 1, 1, 2, 5, 3, 5};
__device__ const int d_act [8] = {2, 1, 1, 3, 0, 2, 0, 1};  // 0=tanh 1=relu 2=sigmoid 3=id
__device__ const int d_snode[4][3] = {{0,0,0},{1,2,3},{4,6,0},{5,7,0}};
__device__ const int d_scnt[4] = {1, 3, 2, 2};

// ---- packed f32x2 (Blackwell) ----
__device__ __forceinline__ u64_t pack2(float lo, float hi) {
    u64_t r; asm("mov.b64 %0, {%1, %2};" : "=l"(r) : "f"(lo), "f"(hi)); return r;
}
__device__ __forceinline__ void fma2(u64_t& d, u64_t a, u64_t b) {
    asm("fma.rn.f32x2 %0, %1, %2, %3;" : "=l"(d) : "l"(a), "l"(b), "l"(d));
}
__device__ __forceinline__ u64_t add2(u64_t a, u64_t b) {
    u64_t d; asm("add.rn.f32x2 %0, %1, %2;" : "=l"(d) : "l"(a), "l"(b)); return d;
}
__device__ __forceinline__ float2 unp2(u64_t v) {
    float x, y; asm("mov.b64 {%0, %1}, %2;" : "=f"(x), "=f"(y) : "l"(v));
    return make_float2(x, y);
}

__device__ __forceinline__ float sigm(float x) { return 1.f / (1.f + expf(-x)); }
__device__ __forceinline__ float actf(int code, float x) {
    switch (code) {
        case 0:  return tanhf(x);
        case 1:  return fmaxf(x, 0.f);
        case 2:  return sigm(x);
        default: return x;
    }
}

// Monotonic-generation grid barrier: needs no reset, safe across graph replays.
__device__ __forceinline__ void grid_sync() {
    __syncthreads();
    if (threadIdx.x == 0) {
        __threadfence();
        unsigned arr = atomicAdd(&g_count, 1u) + 1u;
        unsigned want = (arr + NCTA - 1u) / NCTA;
        if (arr % NCTA == 0u) atomicAdd(&g_gen, 1u);
        while (*((volatile unsigned*)&g_gen) < want) { }
        __threadfence();
    }
    __syncthreads();
}

// One 8-col x 64-row tile of out = gate(Sin) with pre-act = x @ W  (W: [K][2048], c|h halves).
// x is transposed [k][64]; k<Ka from xA, else xB (warp k-slices never straddle Ka).
__device__ __forceinline__ void gemm_tile(
    const float* __restrict__ W, const float* __restrict__ xA,
    const float* __restrict__ xB, int Ka, int K,
    const float* __restrict__ gateT, float* __restrict__ outT,
    int j0, int act, u64_t* red)
{
    const int lane = threadIdx.x & 31;
    const int warp = threadIdx.x >> 5;
    const int ct = lane & 1;           // col-thread: 4 cols each
    const int g  = lane >> 1;          // row-group: 4 rows each (16 groups = 64 rows)
    const int colbase = j0 + ct * 4;
    const int rowbase = g * 4;
    const int kslice = K >> 3;
    const int kbeg = warp * kslice;

    const float* xp = (kbeg < Ka) ? (xA + (size_t)kbeg * Bb)
                                  : (xB + (size_t)(kbeg - Ka) * Bb);
    const float* wp = W + (size_t)kbeg * K2H + colbase;

    u64_t acc[4][2][2];                // [col][rowpair][half]
    #pragma unroll
    for (int c = 0; c < 4; c++)
        #pragma unroll
        for (int rp = 0; rp < 2; rp++) { acc[c][rp][0] = 0ull; acc[c][rp][1] = 0ull; }

    #pragma unroll 4
    for (int k = 0; k < kslice; k++) {
        u64_t x0 = *(const u64_t*)(xp + rowbase);        // rows rowbase, rowbase+1
        u64_t x1 = *(const u64_t*)(xp + rowbase + 2);    // rows rowbase+2, +3
        float4 wc = *(const float4*)(wp);                // c-half weights, 4 cols
        float4 wh = *(const float4*)(wp + Hh);           // h-half weights
        u64_t w;
        w = pack2(wc.x, wc.x); fma2(acc[0][0][0], w, x0); fma2(acc[0][1][0], w, x1);
        w = pack2(wc.y, wc.y); fma2(acc[1][0][0], w, x0); fma2(acc[1][1][0], w, x1);
        w = pack2(wc.z, wc.z); fma2(acc[2][0][0], w, x0); fma2(acc[2][1][0], w, x1);
        w = pack2(wc.w, wc.w); fma2(acc[3][0][0], w, x0); fma2(acc[3][1][0], w, x1);
        w = pack2(wh.x, wh.x); fma2(acc[0][0][1], w, x0); fma2(acc[0][1][1], w, x1);
        w = pack2(wh.y, wh.y); fma2(acc[1][0][1], w, x0); fma2(acc[1][1][1], w, x1);
        w = pack2(wh.z, wh.z); fma2(acc[2][0][1], w, x0); fma2(acc[2][1][1], w, x1);
        w = pack2(wh.w, wh.w); fma2(acc[3][0][1], w, x0); fma2(acc[3][1][1], w, x1);
        xp += Bb; wp += K2H;
    }

    // partials to smem
    u64_t* my = red + ((size_t)(warp * 32 + lane)) * 16;
    #pragma unroll
    for (int c = 0; c < 4; c++)
        #pragma unroll
        for (int rp = 0; rp < 2; rp++) {
            my[(c * 2 + rp) * 2 + 0] = acc[c][rp][0];
            my[(c * 2 + rp) * 2 + 1] = acc[c][rp][1];
        }
    __syncthreads();

    // cross-warp reduce + activation + gate + store. thread -> (lane_r, c, rp)
    {
        const int t = threadIdx.x;
        const int lr = t >> 3;
        const int c  = (t >> 1) & 3;
        const int rp = t & 1;
        const int ic = (c * 2 + rp) * 2;
        u64_t sc = 0ull, sh = 0ull;
        #pragma unroll
        for (int w2 = 0; w2 < 8; w2++) {
            const u64_t* r = red + ((size_t)(w2 * 32 + lr)) * 16;
            sc = add2(sc, r[ic]);
            sh = add2(sh, r[ic + 1]);
        }
        float2 cc = unp2(sc), hh = unp2(sh);
        const int col = j0 + (lr & 1) * 4 + c;
        const int row = (lr >> 1) * 4 + rp * 2;
        const size_t o0 = (size_t)col * Bb + row;
        float sp0 = gateT[o0], sp1 = gateT[o0 + 1];
        float cv0 = sigm(cc.x), cv1 = sigm(cc.y);
        float hv0 = actf(act, hh.x), hv1 = actf(act, hh.y);
        float2 res = make_float2(sp0 + cv0 * (hv0 - sp0), sp1 + cv1 * (hv1 - sp1));
        *(float2*)(outT + o0) = res;
    }
    __syncthreads();
}

__global__ __launch_bounds__(NTHR, 1) void darts_persistent_kernel(
    const int* __restrict__ X, const float* __restrict__ hidden,
    const float* __restrict__ emb, const float* __restrict__ W0,
    const float* __restrict__ Ws, const float* __restrict__ Wout,
    const float* __restrict__ bout, float* __restrict__ out, int out_size)
{
    __shared__ u64_t red[8 * 32 * 16];   // 32 KB cross-warp reduction buffer
    const int cta = blockIdx.x;
    const int tid = threadIdx.x;

    // init: g_hT (transposed hidden) and embT for t=0
    for (int i = tid; i < 512; i += NTHR) {
        int idx = cta * 512 + i;
        int k = idx >> 6, row = idx & 63;
        g_hT[idx] = hidden[(size_t)row * Hh + k];
        int tok = __ldg(&X[row]);
        g_embT[idx] = __ldg(&emb[(size_t)tok * Hh + k]);
    }
    grid_sync();

    for (int t = 0; t < TSTEPS; t++) {
        // S0: s0 from [emb ; h] @ W0, gate base = h, act = tanh
        gemm_tile(W0, g_embT, g_hT, Hh, K2H, g_hT, g_sT[0], cta * 8, 0, red);
        grid_sync();

        // S1..S4: DAG levels
        #pragma unroll
        for (int s = 0; s < 4; s++) {
            for (int m = 0; m < d_scnt[s]; m++) {
                int node = d_snode[s][m];
                const float* Sin = g_sT[d_pred[node]];
                gemm_tile(Ws + (size_t)node * Hh * K2H, Sin, Sin, Hh, Hh,
                          Sin, g_sT[node + 1], cta * 8, d_act[node], red);
            }
            grid_sync();
        }

        // combine: h = mean(s1..s8); also gather embT for t+1
        for (int i = tid; i < 512; i += NTHR) {
            int idx = cta * 512 + i;
            float s = 0.f;
            #pragma unroll
            for (int n = 1; n <= 8; n++) s += g_sT[n][idx];
            g_hT[idx] = s * 0.125f;
            if (t + 1 < TSTEPS) {
                int k = idx >> 6, row = idx & 63;
                int tok = __ldg(&X[(t + 1) * Bb + row]);
                g_embT[idx] = __ldg(&emb[(size_t)tok * Hh + k]);
            }
        }
        grid_sync();
    }

    // head: a_hat = h @ W_out + b_out; probs = softmax (4-wide, lane-aligned groups)
    if (cta == 0) {
        int b = tid >> 2, o = tid & 3;
        float acc = 0.f;
        for (int k = 0; k < Hh; k++) acc += g_hT[(size_t)k * Bb + b] * Wout[k * 4 + o];
        acc += bout[o];
        float m = acc;
        m = fmaxf(m, __shfl_xor_sync(0xFFFFFFFFu, m, 1));
        m = fmaxf(m, __shfl_xor_sync(0xFFFFFFFFu, m, 2));
        float e = expf(acc - m);
        float ssum = e;
        ssum += __shfl_xor_sync(0xFFFFFFFFu, ssum, 1);
        ssum += __shfl_xor_sync(0xFFFFFFFFu, ssum, 2);
        out[b * 4 + o] = acc;
        if (out_size >= 512) out[256 + b * 4 + o] = e / ssum;
    }
}

extern "C" void kernel_launch(void* const* d_in, const int* in_sizes, int n_in,
                              void* d_out, int out_size) {
    const int*   X      = (const int*)d_in[0];
    const float* hidden = (const float*)d_in[1];
    const float* emb    = (const float*)d_in[2];
    const float* W0     = (const float*)d_in[3];
    const float* Ws     = (const float*)d_in[4];
    const float* W_out  = (const float*)d_in[5];
    const float* b_out  = (const float*)d_in[6];
    (void)in_sizes; (void)n_in;

    darts_persistent_kernel<<<NCTA, NTHR>>>(X, hidden, emb, W0, Ws, W_out, b_out,
                                            (float*)d_out, out_size);
}

// round 3
// speedup vs baseline: 1.3206x; 1.3206x over previous
#include <cuda_runtime.h>

#define NCTA 128
#define NTHR 512
#define NWARP 16
#define TSTEPS 512
#define Bb 64
#define Hh 1024
#define K2H 2048

typedef unsigned long long u64_t;

// Persistent device state (allocation-free scratch). All transposed: [col][row], row=batch.
__device__ float g_sT[9][Hh * Bb];
__device__ float g_hT[Hh * Bb];
__device__ float g_embT[Hh * Bb];
__device__ unsigned g_count = 0;   // monotonic across barriers AND graph replays
__device__ unsigned g_gen = 0;

// DAG metadata: node i uses Ws[i], input states[pred[i]], output states[i+1].
__device__ const int d_pred[8] = {0, 1, 1, 1, 2, 5, 3, 5};
__device__ const int d_act [8] = {2, 1, 1, 3, 0, 2, 0, 1};  // 0=tanh 1=relu 2=sigmoid 3=id
__device__ const int d_snode[4][3] = {{0,0,0},{1,2,3},{4,6,0},{5,7,0}};
__device__ const int d_scnt[4] = {1, 3, 2, 2};

// ---- packed f32x2 (Blackwell) ----
__device__ __forceinline__ u64_t pack2(float lo, float hi) {
    u64_t r; asm("mov.b64 %0, {%1, %2};" : "=l"(r) : "f"(lo), "f"(hi)); return r;
}
__device__ __forceinline__ void fma2(u64_t& d, u64_t a, u64_t b) {
    asm("fma.rn.f32x2 %0, %1, %2, %3;" : "=l"(d) : "l"(a), "l"(b), "l"(d));
}
__device__ __forceinline__ u64_t add2(u64_t a, u64_t b) {
    u64_t d; asm("add.rn.f32x2 %0, %1, %2;" : "=l"(d) : "l"(a), "l"(b)); return d;
}

__device__ __forceinline__ float sigm(float x) { return 1.f / (1.f + expf(-x)); }
__device__ __forceinline__ float actf(int code, float x) {
    switch (code) {
        case 0:  return tanhf(x);
        case 1:  return fmaxf(x, 0.f);
        case 2:  return sigm(x);
        default: return x;
    }
}

// Monotonic-generation grid barrier: no reset needed, safe across graph replays.
__device__ __forceinline__ void grid_sync() {
    __syncthreads();
    if (threadIdx.x == 0) {
        __threadfence();
        unsigned arr = atomicAdd(&g_count, 1u) + 1u;
        unsigned want = (arr + NCTA - 1u) / NCTA;
        if (arr % NCTA == 0u) atomicAdd(&g_gen, 1u);
        while (*((volatile unsigned*)&g_gen) < want) { }
        __threadfence();
    }
    __syncthreads();
}

// One 8-col x 64-row output tile: out = gated(Sin) with pre-act = x @ W (W:[K][2048], c|h halves).
// x transposed [k][64]; k<Ka from xA else xB (warp k-slices never straddle Ka).
// 16 warps split K; two-stage smem reduction (32KB).
__device__ __forceinline__ void gemm_tile(
    const float* __restrict__ W, const float* __restrict__ xA,
    const float* __restrict__ xB, int Ka, int K,
    const float* __restrict__ gateT, float* __restrict__ outT,
    int j0, int act, u64_t* red)
{
    const int lane = threadIdx.x & 31;
    const int warp = threadIdx.x >> 5;
    const int ct = lane & 1;           // 2 col-threads: 4 cols each
    const int g  = lane >> 1;          // 16 row-groups: 4 rows each
    const int colbase = j0 + ct * 4;
    const int rowbase = g * 4;
    const int kslice = K >> 4;         // 16-way K split
    const int kbeg = warp * kslice;

    const float* xp = (kbeg < Ka) ? (xA + (size_t)kbeg * Bb)
                                  : (xB + (size_t)(kbeg - Ka) * Bb);
    const float* wp = W + (size_t)kbeg * K2H + colbase;

    u64_t acc[4][2][2];                // [row r][colpair cp][half h] ; u64 = cols (2cp, 2cp+1)
    #pragma unroll
    for (int r = 0; r < 4; r++)
        #pragma unroll
        for (int cp = 0; cp < 2; cp++) { acc[r][cp][0] = 0ull; acc[r][cp][1] = 0ull; }

    #pragma unroll 4
    for (int k = 0; k < kslice; k++) {
        float4 xv = *(const float4*)(xp + rowbase);          // 4 rows
        const u64_t* wcp = (const u64_t*)wp;                 // c-half: cols (0,1),(2,3)
        const u64_t* whp = (const u64_t*)(wp + Hh);          // h-half
        u64_t wc0 = wcp[0], wc1 = wcp[1];
        u64_t wh0 = whp[0], wh1 = whp[1];
        u64_t xb;
        xb = pack2(xv.x, xv.x);
        fma2(acc[0][0][0], xb, wc0); fma2(acc[0][1][0], xb, wc1);
        fma2(acc[0][0][1], xb, wh0); fma2(acc[0][1][1], xb, wh1);
        xb = pack2(xv.y, xv.y);
        fma2(acc[1][0][0], xb, wc0); fma2(acc[1][1][0], xb, wc1);
        fma2(acc[1][0][1], xb, wh0); fma2(acc[1][1][1], xb, wh1);
        xb = pack2(xv.z, xv.z);
        fma2(acc[2][0][0], xb, wc0); fma2(acc[2][1][0], xb, wc1);
        fma2(acc[2][0][1], xb, wh0); fma2(acc[2][1][1], xb, wh1);
        xb = pack2(xv.w, xv.w);
        fma2(acc[3][0][0], xb, wc0); fma2(acc[3][1][0], xb, wc1);
        fma2(acc[3][0][1], xb, wh0); fma2(acc[3][1][1], xb, wh1);
        xp += Bb; wp += K2H;
    }

    // Stage 1: warps 8..15 store partials into slot (warp-8).
    if (warp >= 8) {
        u64_t* my = red + ((size_t)((warp - 8) * 32 + lane)) * 16;
        #pragma unroll
        for (int r = 0; r < 4; r++)
            #pragma unroll
            for (int cp = 0; cp < 2; cp++) {
                my[(r * 4 + cp * 2) + 0] = acc[r][cp][0];
                my[(r * 4 + cp * 2) + 1] = acc[r][cp][1];
            }
    }
    __syncthreads();

    // Stage 2: warps 0..7 add partner partials, store combined into slot warp.
    if (warp < 8) {
        u64_t* my = red + ((size_t)(warp * 32 + lane)) * 16;
        #pragma unroll
        for (int r = 0; r < 4; r++)
            #pragma unroll
            for (int cp = 0; cp < 2; cp++) {
                int i0 = r * 4 + cp * 2;
                my[i0 + 0] = add2(my[i0 + 0], acc[r][cp][0]);
                my[i0 + 1] = add2(my[i0 + 1], acc[r][cp][1]);
            }
    }
    __syncthreads();

    // Stage 3: 512 threads finalize 512 outputs (8 cols x 64 rows).
    {
        const int t   = threadIdx.x;
        const int c8  = t & 7;          // col within tile
        const int row = t >> 3;         // 0..63
        const int sct = c8 >> 2;
        const int cp  = (c8 >> 1) & 1;
        const int par = c8 & 1;
        const int sg  = row >> 2;
        const int r   = row & 3;
        const int slane = sg * 2 + sct;
        const float* redf = (const float*)red;
        const int fbase = slane * 32 + (r * 4 + cp * 2) * 2 + par;  // within a slot

        float sc = 0.f, sh = 0.f;
        #pragma unroll
        for (int s = 0; s < 8; s++) {
            const float* rp = redf + (size_t)s * 32 * 32 + fbase;
            sc += rp[0];
            sh += rp[2];
        }
        const int col = j0 + c8;
        const size_t o = (size_t)col * Bb + row;
        float sp = gateT[o];
        float cv = sigm(sc);
        float hv = actf(act, sh);
        outT[o] = sp + cv * (hv - sp);
    }
    __syncthreads();
}

__global__ __launch_bounds__(NTHR, 1) void darts_persistent_kernel(
    const int* __restrict__ X, const float* __restrict__ hidden,
    const float* __restrict__ emb, const float* __restrict__ W0,
    const float* __restrict__ Ws, const float* __restrict__ Wout,
    const float* __restrict__ bout, float* __restrict__ out, int out_size)
{
    __shared__ u64_t red[8 * 32 * 16];   // 32 KB two-stage reduction buffer
    const int cta = blockIdx.x;
    const int tid = threadIdx.x;

    // init: transposed hidden and embT for t=0
    {
        int idx = cta * 512 + tid;
        int k = idx >> 6, row = idx & 63;
        g_hT[idx] = hidden[(size_t)row * Hh + k];
        int tok = __ldg(&X[row]);
        g_embT[idx] = __ldg(&emb[(size_t)tok * Hh + k]);
    }
    grid_sync();

    for (int t = 0; t < TSTEPS; t++) {
        // S0: s0 from [emb ; h] @ W0, gate base = h, act = tanh
        gemm_tile(W0, g_embT, g_hT, Hh, K2H, g_hT, g_sT[0], cta * 8, 0, red);
        grid_sync();

        // DAG levels
        #pragma unroll
        for (int s = 0; s < 4; s++) {
            for (int m = 0; m < d_scnt[s]; m++) {
                int node = d_snode[s][m];
                const float* Sin = g_sT[d_pred[node]];
                gemm_tile(Ws + (size_t)node * Hh * K2H, Sin, Sin, Hh, Hh,
                          Sin, g_sT[node + 1], cta * 8, d_act[node], red);
            }
            grid_sync();
        }

        // combine: h = mean(s1..s8); gather embT for t+1
        {
            int idx = cta * 512 + tid;
            float s = 0.f;
            #pragma unroll
            for (int n = 1; n <= 8; n++) s += g_sT[n][idx];
            g_hT[idx] = s * 0.125f;
            if (t + 1 < TSTEPS) {
                int k = idx >> 6, row = idx & 63;
                int tok = __ldg(&X[(t + 1) * Bb + row]);
                g_embT[idx] = __ldg(&emb[(size_t)tok * Hh + k]);
            }
        }
        grid_sync();
    }

    // head: a_hat = h @ W_out + b_out; probs = softmax (4-wide, lane-aligned groups)
    if (cta == 0 && tid < 256) {
        int b = tid >> 2, o = tid & 3;
        float acc = 0.f;
        for (int k = 0; k < Hh; k++) acc += g_hT[(size_t)k * Bb + b] * Wout[k * 4 + o];
        acc += bout[o];
        float m = acc;
        m = fmaxf(m, __shfl_xor_sync(0xFFFFFFFFu, m, 1));
        m = fmaxf(m, __shfl_xor_sync(0xFFFFFFFFu, m, 2));
        float e = expf(acc - m);
        float ssum = e;
        ssum += __shfl_xor_sync(0xFFFFFFFFu, ssum, 1);
        ssum += __shfl_xor_sync(0xFFFFFFFFu, ssum, 2);
        out[b * 4 + o] = acc;
        if (out_size >= 512) out[256 + b * 4 + o] = e / ssum;
    }
}

extern "C" void kernel_launch(void* const* d_in, const int* in_sizes, int n_in,
                              void* d_out, int out_size) {
    const int*   X      = (const int*)d_in[0];
    const float* hidden = (const float*)d_in[1];
    const float* emb    = (const float*)d_in[2];
    const float* W0     = (const float*)d_in[3];
    const float* Ws     = (const float*)d_in[4];
    const float* W_out  = (const float*)d_in[5];
    const float* b_out  = (const float*)d_in[6];
    (void)in_sizes; (void)n_in;

    darts_persistent_kernel<<<NCTA, NTHR>>>(X, hidden, emb, W0, Ws, W_out, b_out,
                                            (float*)d_out, out_size);
}